// round 2
// baseline (speedup 1.0000x reference)
#include <cuda_runtime.h>
#include <cstdint>

#define BATCH 64
#define T0    2048
#define DM    128
#define G3    384
#define NW    64
#define WS    64
#define PL    4

// ---------------- device scratch (no allocations allowed) ----------------
__device__ float g_xbuf[BATCH][T0 + 8];   // growing sequence per batch elem
__device__ float g_H[BATCH][DM];          // main GRU hidden state
__device__ float g_E[BATCH * NW];         // attention logits
__device__ float g_o[BATCH];              // o = H@Wd^T + bd
__device__ int   g_starts[PL * BATCH * NW];

// ---------------- threefry2x32 (bit-exact JAX PRNG) ----------------
__device__ __forceinline__ void tf2x32(uint32_t k0, uint32_t k1,
                                       uint32_t x0, uint32_t x1,
                                       uint32_t& y0, uint32_t& y1) {
    uint32_t ks2 = k0 ^ k1 ^ 0x1BD11BDAu;
    uint32_t ks[3] = {k0, k1, ks2};
    x0 += k0; x1 += k1;
    const int R0[4] = {13, 15, 26, 6};
    const int R1[4] = {17, 29, 16, 24};
#pragma unroll
    for (int i = 0; i < 5; i++) {
#pragma unroll
        for (int r = 0; r < 4; r++) {
            int d = (i % 2 == 0) ? R0[r] : R1[r];
            x0 += x1;
            x1 = (x1 << d) | (x1 >> (32 - d));
            x1 ^= x0;
        }
        x0 += ks[(i + 1) % 3];
        x1 += ks[(i + 2) % 3] + (uint32_t)(i + 1);
    }
    y0 = x0; y1 = x1;
}

// starts[i][b][m] = jax.random.randint(fold_in(key(42), i), (64,64), 0, T_i-64)
__global__ void starts_kernel() {
    int tid = blockIdx.x * blockDim.x + threadIdx.x;   // 4 * 2048 threads
    if (tid >= PL * 2048) return;
    int i  = tid >> 11;
    int jj = tid & 2047;

    // fold_in(key(42)=(0,42), i): threefry(key, [0, i])
    uint32_t f0, f1;
    tf2x32(0u, 42u, 0u, (uint32_t)i, f0, f1);
    // split(key_i, 2): counts [0,1,2,3] -> x0=[0,1], x1=[2,3]
    uint32_t a0, b0, a1, b1;
    tf2x32(f0, f1, 0u, 2u, a0, b0);
    tf2x32(f0, f1, 1u, 3u, a1, b1);
    // k1=(a0,a1) -> higher bits, k2=(b0,b1) -> lower bits

    uint32_t span = 1984u + (uint32_t)i;               // (2048+i) - 64
    uint32_t mult = 65536u % span;
    mult = (mult * mult) % span;                       // 2^32 % span

    // random_bits shape 4096: x0 = counts[0:2048], x1 = counts[2048:4096]
    uint32_t hc, hd, lc, ld;
    tf2x32(a0, a1, (uint32_t)jj, (uint32_t)(2048 + jj), hc, hd);
    tf2x32(b0, b1, (uint32_t)jj, (uint32_t)(2048 + jj), lc, ld);

    uint32_t o1 = ((hc % span) * mult + (lc % span)) % span;
    uint32_t o2 = ((hd % span) * mult + (ld % span)) % span;
    g_starts[i * 4096 + jj]        = (int)o1;
    g_starts[i * 4096 + 2048 + jj] = (int)o2;
}

// ---------------- init: copy batch_x into the growing buffer ----------------
__global__ void copy_x_kernel(const float* __restrict__ batch_x) {
    int idx = blockIdx.x * blockDim.x + threadIdx.x;
    if (idx < BATCH * T0) {
        int b = idx / T0, t = idx % T0;
        g_xbuf[b][t] = batch_x[idx];
    }
}

__device__ __forceinline__ float sigf(float x) {
    return __fdividef(1.f, 1.f + __expf(-x));
}
__device__ __forceinline__ float tanhfast(float x) {
    // tanh(x) = 1 - 2/(1+e^{2x});  safe at both extremes
    return 1.f - __fdividef(2.f, 1.f + __expf(2.f * x));
}

// ---------------- main GRU: one CTA per batch element, Wh rows in registers ----
__global__ __launch_bounds__(G3, 1)
void main_gru_kernel(const float* __restrict__ Wh, const float* __restrict__ Wi,
                     const float* __restrict__ bi, const float* __restrict__ bh,
                     const float* __restrict__ Wd, const float* __restrict__ bd,
                     int pass, int Tpass) {
    int b = blockIdx.x;
    int j = threadIdx.x;             // 0..383, gate-output index

    __shared__ float hs[DM];
    __shared__ float gh[G3];

    // weights for gate output j (row j of Wh), 128 floats in registers
    float4 w[32];
    const float4* Wr = (const float4*)(Wh + j * DM);
#pragma unroll
    for (int q = 0; q < 32; q++) w[q] = Wr[q];
    float bhj = bh[j];

    float wiR = 0, wiZ = 0, wiN = 0, biR = 0, biZ = 0, biN = 0, hreg = 0;
    if (j < DM) {
        wiR = Wi[j]; wiZ = Wi[DM + j]; wiN = Wi[2 * DM + j];
        biR = bi[j]; biZ = bi[DM + j]; biN = bi[2 * DM + j];
        hreg = (pass == 0) ? 0.f : g_H[b][j];
        hs[j] = hreg;
    }
    __syncthreads();

    const float* xb = g_xbuf[b];
    for (int t = 0; t < Tpass; t++) {
        float xt = xb[t];
        const float4* h4 = (const float4*)hs;
        float a0 = 0, a1 = 0, a2 = 0, a3 = 0;
#pragma unroll
        for (int q = 0; q < 32; q++) {
            float4 hv = h4[q];
            a0 += w[q].x * hv.x; a1 += w[q].y * hv.y;
            a2 += w[q].z * hv.z; a3 += w[q].w * hv.w;
        }
        gh[j] = (a0 + a1) + (a2 + a3) + bhj;
        __syncthreads();
        if (j < DM) {
            float ghr = gh[j], ghz = gh[DM + j], ghn = gh[2 * DM + j];
            float r = sigf(xt * wiR + biR + ghr);
            float z = sigf(xt * wiZ + biZ + ghz);
            float n = tanhfast(xt * wiN + biN + r * ghn);
            hreg = (1.f - z) * n + z * hreg;
            hs[j] = hreg;
        }
        __syncthreads();
    }

    if (j < DM) {
        g_H[b][j] = hreg;
        gh[j] = hreg * Wd[j];
    }
    __syncthreads();
    if (j == 0) {
        float s = bd[0];
        for (int k = 0; k < DM; k++) s += gh[k];
        g_o[b] = s;
    }
}

// ---------------- window GRU: 8 windows per CTA, 512 CTAs ----------------
#define WPB 8
__global__ __launch_bounds__(G3, 1)
void win_gru_kernel(const float* __restrict__ Wh, const float* __restrict__ Wi,
                    const float* __restrict__ bi, const float* __restrict__ bh,
                    int step) {
    int c = blockIdx.x;
    int j = threadIdx.x;

    __shared__ float hs[WPB][DM];
    __shared__ float gh[WPB][G3];
    __shared__ float xs[WPB];
    __shared__ int   sst[WPB];
    __shared__ int   sb[WPB];

    float4 w[32];
    const float4* Wr = (const float4*)(Wh + j * DM);
#pragma unroll
    for (int q = 0; q < 32; q++) w[q] = Wr[q];
    float bhj = bh[j];

    float wiR = 0, wiZ = 0, wiN = 0, biR = 0, biZ = 0, biN = 0;
    if (j < DM) {
        wiR = Wi[j]; wiZ = Wi[DM + j]; wiN = Wi[2 * DM + j];
        biR = bi[j]; biZ = bi[DM + j]; biN = bi[2 * DM + j];
        for (int g = 0; g < WPB; g++) hs[g][j] = 0.f;
    }
    if (j < WPB) {
        int wdx = c * WPB + j;
        sst[j] = g_starts[step * 4096 + wdx];
        sb[j]  = wdx >> 6;
    }
    __syncthreads();

    for (int t = 0; t < WS; t++) {
        if (j < WPB) xs[j] = g_xbuf[sb[j]][sst[j] + t];
        for (int g = 0; g < WPB; g++) {
            const float4* h4 = (const float4*)hs[g];
            float a0 = 0, a1 = 0, a2 = 0, a3 = 0;
#pragma unroll
            for (int q = 0; q < 32; q++) {
                float4 hv = h4[q];
                a0 += w[q].x * hv.x; a1 += w[q].y * hv.y;
                a2 += w[q].z * hv.z; a3 += w[q].w * hv.w;
            }
            gh[g][j] = (a0 + a1) + (a2 + a3) + bhj;
        }
        __syncthreads();
        if (j < DM) {
            for (int g = 0; g < WPB; g++) {
                float xt = xs[g];
                float ghr = gh[g][j], ghz = gh[g][DM + j], ghn = gh[g][2 * DM + j];
                float r = sigf(xt * wiR + biR + ghr);
                float z = sigf(xt * wiZ + biZ + ghz);
                float n = tanhfast(xt * wiN + biN + r * ghn);
                hs[g][j] = (1.f - z) * n + z * hs[g][j];
            }
        }
        __syncthreads();
    }

    // attention logits: E[w] = dot(H[b], S_w)
    int wp = j >> 5, lane = j & 31;
    if (wp < WPB) {
        int wdx = c * WPB + wp;
        int b = wdx >> 6;
        float p = 0;
        for (int k = lane; k < DM; k += 32) p += g_H[b][k] * hs[wp][k];
#pragma unroll
        for (int o = 16; o > 0; o >>= 1) p += __shfl_xor_sync(0xffffffffu, p, o);
        if (lane == 0) g_E[wdx] = p;
    }
}

// ---------------- finalize: stats, softmax, u, append y ----------------
__global__ void finalize_kernel(const float* __restrict__ Wc, const float* __restrict__ bc,
                                int step, int T, float* __restrict__ out) {
    int b = blockIdx.x;
    int j = threadIdx.x;   // 128 threads

    __shared__ double rd1[128], rd2[128];
    __shared__ float sE[NW], sQ[NW];
    __shared__ float s_thr;

    const float* xb = g_xbuf[b];
    double d1 = 0, d2 = 0;
    for (int t = j; t < T; t += 128) {
        float v = xb[t];
        d1 += (double)v;
        d2 += (double)v * (double)v;
    }
    rd1[j] = d1; rd2[j] = d2;
    __syncthreads();
    for (int st = 64; st > 0; st >>= 1) {
        if (j < st) { rd1[j] += rd1[j + st]; rd2[j] += rd2[j + st]; }
        __syncthreads();
    }
    if (j == 0) {
        double mean = rd1[0] / (double)T;
        double var = (rd2[0] - rd1[0] * mean) / (double)(T - 1);
        if (var < 0) var = 0;
        s_thr = (float)(mean + 1.48 * sqrt(var));
    }
    __syncthreads();
    float thr = s_thr;

    if (j < NW) {
        sE[j] = g_E[b * NW + j];
        int st = g_starts[step * 4096 + b * NW + j];
        sQ[j] = (xb[st + WS] > thr) ? 1.f : 0.f;
    }
    __syncthreads();

    if (j == 0) {
        float mx = -1e30f;
        for (int m = 0; m < NW; m++) mx = fmaxf(mx, sE[m]);
        float ssum = 0.f, s = 0.f;
        for (int m = 0; m < NW; m++) {
            float a = __expf(sE[m] - mx);
            ssum += a;
            if (sQ[m] > 0.5f) s += a;
        }
        s /= ssum;
        float u = 1.f / (1.f + __expf(-(s * Wc[0] + bc[0])));
        float y = g_o[b] + u;
        g_xbuf[b][T] = y;                       // append
        out[b * PL + step]                 = y; // pred  (B,4,1)
        out[BATCH * PL + b * PL + step]    = u; // us    (B,4,1)
    }
}

// ---------------- launch ----------------
extern "C" void kernel_launch(void* const* d_in, const int* in_sizes, int n_in,
                              void* d_out, int out_size) {
    const float* batch_x = (const float*)d_in[0];
    const float* Wi_g = (const float*)d_in[4];
    const float* Wh_g = (const float*)d_in[5];
    const float* bi_g = (const float*)d_in[6];
    const float* bh_g = (const float*)d_in[7];
    const float* Wi_w = (const float*)d_in[8];
    const float* Wh_w = (const float*)d_in[9];
    const float* bi_w = (const float*)d_in[10];
    const float* bh_w = (const float*)d_in[11];
    const float* Wd   = (const float*)d_in[12];
    const float* bd   = (const float*)d_in[13];
    const float* Wc   = (const float*)d_in[16];
    const float* bc   = (const float*)d_in[17];
    float* out = (float*)d_out;

    copy_x_kernel<<<(BATCH * T0 + 511) / 512, 512>>>(batch_x);
    starts_kernel<<<(PL * 2048 + 255) / 256, 256>>>();

    for (int i = 0; i < PL; i++) {
        int T = T0 + i;                      // current sequence length
        int Tpass = (i == 0) ? T0 : (T - 1); // re-encode length
        main_gru_kernel<<<BATCH, G3>>>(Wh_g, Wi_g, bi_g, bh_g, Wd, bd, i, Tpass);
        win_gru_kernel<<<BATCH * NW / WPB, G3>>>(Wh_w, Wi_w, bi_w, bh_w, i);
        finalize_kernel<<<BATCH, 128>>>(Wc, bc, i, T, out);
    }
}

// round 5
// speedup vs baseline: 1.4631x; 1.4631x over previous
#include <cuda_runtime.h>
#include <cstdint>

#define BATCH 64
#define T0    2048
#define DM    128
#define G3    384
#define NW    64
#define WS    64
#define PL    4
#define WPB   8

// ---------------- device scratch (no allocations allowed) ----------------
__device__ float g_xbuf[BATCH][T0 + 8];      // growing sequence per batch elem
__device__ float g_H[BATCH][DM];             // main GRU hidden state
__device__ float g_S[BATCH * NW][DM];        // window GRU final hidden states
__device__ float g_o[BATCH];                 // o = H@Wd^T + bd
__device__ int   g_starts[PL * BATCH * NW];

// ---------------- packed f32x2 FMA (bit-identical pairing) ----------------
__device__ __forceinline__ unsigned long long ffma2(unsigned long long a,
                                                    unsigned long long b,
                                                    unsigned long long c) {
    unsigned long long d;
    asm("fma.rn.f32x2 %0, %1, %2, %3;" : "=l"(d) : "l"(a), "l"(b), "l"(c));
    return d;
}
__device__ __forceinline__ unsigned long long d2l(double v) {
    return __double_as_longlong(v);
}
__device__ __forceinline__ float2 unpack2(unsigned long long v) {
    float2 f;
    f.x = __uint_as_float((unsigned)(v & 0xffffffffu));
    f.y = __uint_as_float((unsigned)(v >> 32));
    return f;
}

// ---------------- threefry2x32 (bit-exact JAX PRNG) ----------------
__device__ __forceinline__ void tf2x32(uint32_t k0, uint32_t k1,
                                       uint32_t x0, uint32_t x1,
                                       uint32_t& y0, uint32_t& y1) {
    uint32_t ks2 = k0 ^ k1 ^ 0x1BD11BDAu;
    uint32_t ks[3] = {k0, k1, ks2};
    x0 += k0; x1 += k1;
    const int R0[4] = {13, 15, 26, 6};
    const int R1[4] = {17, 29, 16, 24};
#pragma unroll
    for (int i = 0; i < 5; i++) {
#pragma unroll
        for (int r = 0; r < 4; r++) {
            int d = (i % 2 == 0) ? R0[r] : R1[r];
            x0 += x1;
            x1 = (x1 << d) | (x1 >> (32 - d));
            x1 ^= x0;
        }
        x0 += ks[(i + 1) % 3];
        x1 += ks[(i + 2) % 3] + (uint32_t)(i + 1);
    }
    y0 = x0; y1 = x1;
}

__global__ void starts_kernel() {
    int tid = blockIdx.x * blockDim.x + threadIdx.x;
    if (tid >= PL * 2048) return;
    int i  = tid >> 11;
    int jj = tid & 2047;

    uint32_t f0, f1;
    tf2x32(0u, 42u, 0u, (uint32_t)i, f0, f1);
    uint32_t a0, b0, a1, b1;
    tf2x32(f0, f1, 0u, 2u, a0, b0);
    tf2x32(f0, f1, 1u, 3u, a1, b1);

    uint32_t span = 1984u + (uint32_t)i;
    uint32_t mult = 65536u % span;
    mult = (mult * mult) % span;

    uint32_t hc, hd, lc, ld;
    tf2x32(a0, a1, (uint32_t)jj, (uint32_t)(2048 + jj), hc, hd);
    tf2x32(b0, b1, (uint32_t)jj, (uint32_t)(2048 + jj), lc, ld);

    uint32_t o1 = ((hc % span) * mult + (lc % span)) % span;
    uint32_t o2 = ((hd % span) * mult + (ld % span)) % span;
    g_starts[i * 4096 + jj]        = (int)o1;
    g_starts[i * 4096 + 2048 + jj] = (int)o2;
}

__global__ void copy_x_kernel(const float* __restrict__ batch_x) {
    int idx = blockIdx.x * blockDim.x + threadIdx.x;
    if (idx < BATCH * T0) {
        int b = idx / T0, t = idx % T0;
        g_xbuf[b][t] = batch_x[idx];
    }
}

__device__ __forceinline__ float sigf(float x) {
    return __fdividef(1.f, 1.f + __expf(-x));
}
__device__ __forceinline__ float tanhfast(float x) {
    return 1.f - __fdividef(2.f, 1.f + __expf(2.f * x));
}

// ---------------- merged step kernel: main GRU (64 CTAs) + window GRU (512 CTAs) ----
__global__ __launch_bounds__(G3, 1)
void step_kernel(const float* __restrict__ Wh_g, const float* __restrict__ Wi_g,
                 const float* __restrict__ bi_g, const float* __restrict__ bh_g,
                 const float* __restrict__ Wd,   const float* __restrict__ bd,
                 const float* __restrict__ Wh_w, const float* __restrict__ Wi_w,
                 const float* __restrict__ bi_w, const float* __restrict__ bh_w,
                 int pass, int Tpass) {
    int j = threadIdx.x;

    // shared pool: big enough for window branch (hs[WPB][DM] + gh[WPB][G3] + extras)
    __shared__ float hs_s[WPB][DM];
    __shared__ float gh_s[WPB][G3];
    __shared__ float xs[WPB];
    __shared__ int   sst[WPB];
    __shared__ int   sb[WPB];

    if (blockIdx.x < BATCH) {
        // ================= MAIN GRU branch =================
        int b = blockIdx.x;
        float* hs = hs_s[0];
        float* gh = gh_s[0];

        // row j of Wh_g packed into 64-bit f32x2 registers
        unsigned long long wlo[32], whi[32];
        const double2* Wr = (const double2*)(Wh_g + j * DM);
#pragma unroll
        for (int q = 0; q < 32; q++) {
            double2 v = Wr[q];
            wlo[q] = d2l(v.x); whi[q] = d2l(v.y);
        }
        float bhj = bh_g[j];

        float wiR = 0, wiZ = 0, wiN = 0, biR = 0, biZ = 0, biN = 0, hreg = 0;
        if (j < DM) {
            wiR = Wi_g[j]; wiZ = Wi_g[DM + j]; wiN = Wi_g[2 * DM + j];
            biR = bi_g[j]; biZ = bi_g[DM + j]; biN = bi_g[2 * DM + j];
            hreg = (pass == 0) ? 0.f : g_H[b][j];
            hs[j] = hreg;
        }
        __syncthreads();

        const float* xb = g_xbuf[b];
        for (int t = 0; t < Tpass; t++) {
            float xt = xb[t];
            const double2* h4 = (const double2*)hs;
            unsigned long long accA = 0ull, accB = 0ull;
#pragma unroll
            for (int q = 0; q < 32; q++) {
                double2 hv = h4[q];
                accA = ffma2(wlo[q], d2l(hv.x), accA);
                accB = ffma2(whi[q], d2l(hv.y), accB);
            }
            float2 A = unpack2(accA), Bv = unpack2(accB);
            gh[j] = (A.x + A.y) + (Bv.x + Bv.y) + bhj;
            __syncthreads();
            if (j < DM) {
                float ghr = gh[j], ghz = gh[DM + j], ghn = gh[2 * DM + j];
                float r = sigf(xt * wiR + biR + ghr);
                float z = sigf(xt * wiZ + biZ + ghz);
                float n = tanhfast(xt * wiN + biN + r * ghn);
                hreg = (1.f - z) * n + z * hreg;
                hs[j] = hreg;
            }
            __syncthreads();
        }

        if (j < DM) {
            g_H[b][j] = hreg;
            gh[j] = hreg * Wd[j];
        }
        __syncthreads();
        if (j == 0) {
            float s = bd[0];
            for (int k = 0; k < DM; k++) s += gh[k];
            g_o[b] = s;
        }
    } else {
        // ================= WINDOW GRU branch =================
        int c = blockIdx.x - BATCH;

        unsigned long long wlo[32], whi[32];
        const double2* Wr = (const double2*)(Wh_w + j * DM);
#pragma unroll
        for (int q = 0; q < 32; q++) {
            double2 v = Wr[q];
            wlo[q] = d2l(v.x); whi[q] = d2l(v.y);
        }
        float bhj = bh_w[j];

        float wiR = 0, wiZ = 0, wiN = 0, biR = 0, biZ = 0, biN = 0;
        if (j < DM) {
            wiR = Wi_w[j]; wiZ = Wi_w[DM + j]; wiN = Wi_w[2 * DM + j];
            biR = bi_w[j]; biZ = bi_w[DM + j]; biN = bi_w[2 * DM + j];
            for (int g = 0; g < WPB; g++) hs_s[g][j] = 0.f;
        }
        if (j < WPB) {
            int wdx = c * WPB + j;
            sst[j] = g_starts[pass * 4096 + wdx];
            sb[j]  = wdx >> 6;
        }
        __syncthreads();

        for (int t = 0; t < WS; t++) {
            if (j < WPB) xs[j] = g_xbuf[sb[j]][sst[j] + t];
#pragma unroll
            for (int g = 0; g < WPB; g++) {
                const double2* h4 = (const double2*)hs_s[g];
                unsigned long long accA = 0ull, accB = 0ull;
#pragma unroll
                for (int q = 0; q < 32; q++) {
                    double2 hv = h4[q];
                    accA = ffma2(wlo[q], d2l(hv.x), accA);
                    accB = ffma2(whi[q], d2l(hv.y), accB);
                }
                float2 A = unpack2(accA), Bv = unpack2(accB);
                gh_s[g][j] = (A.x + A.y) + (Bv.x + Bv.y) + bhj;
            }
            __syncthreads();
            if (j < DM) {
#pragma unroll
                for (int g = 0; g < WPB; g++) {
                    float xt = xs[g];
                    float ghr = gh_s[g][j], ghz = gh_s[g][DM + j], ghn = gh_s[g][2 * DM + j];
                    float r = sigf(xt * wiR + biR + ghr);
                    float z = sigf(xt * wiZ + biZ + ghz);
                    float n = tanhfast(xt * wiN + biN + r * ghn);
                    hs_s[g][j] = (1.f - z) * n + z * hs_s[g][j];
                }
            }
            __syncthreads();
        }

        // spill final hidden states; attention logits move to finalize
        if (j < DM) {
#pragma unroll
            for (int g = 0; g < WPB; g++) g_S[c * WPB + g][j] = hs_s[g][j];
        }
    }
}

// ---------------- finalize: attention logits + stats + softmax + u + append y ----
__global__ void finalize_kernel(const float* __restrict__ Wc, const float* __restrict__ bc,
                                int step, int T, float* __restrict__ out) {
    int b = blockIdx.x;
    int j = threadIdx.x;   // 128 threads

    __shared__ double rd1[128], rd2[128];
    __shared__ float sE[NW], sQ[NW];
    __shared__ float sH[DM];
    __shared__ float s_thr;

    if (j < DM) sH[j] = g_H[b][j];

    const float* xb = g_xbuf[b];
    double d1 = 0, d2 = 0;
    for (int t = j; t < T; t += 128) {
        float v = xb[t];
        d1 += (double)v;
        d2 += (double)v * (double)v;
    }
    rd1[j] = d1; rd2[j] = d2;
    __syncthreads();
    for (int st = 64; st > 0; st >>= 1) {
        if (j < st) { rd1[j] += rd1[j + st]; rd2[j] += rd2[j + st]; }
        __syncthreads();
    }
    if (j == 0) {
        double mean = rd1[0] / (double)T;
        double var = (rd2[0] - rd1[0] * mean) / (double)(T - 1);
        if (var < 0) var = 0;
        s_thr = (float)(mean + 1.48 * sqrt(var));
    }
    __syncthreads();
    float thr = s_thr;

    // attention logits E[m] = dot(H_b, S_{b,m}); lane-strided + xor-reduce
    // (identical summation order to the previously passing kernel)
    int wp = j >> 5, lane = j & 31;
    for (int m = wp; m < NW; m += 4) {
        const float* Sm = g_S[b * NW + m];
        float p = 0;
        for (int k = lane; k < DM; k += 32) p += sH[k] * Sm[k];
#pragma unroll
        for (int o = 16; o > 0; o >>= 1) p += __shfl_xor_sync(0xffffffffu, p, o);
        if (lane == 0) sE[m] = p;
    }

    if (j < NW) {
        int st = g_starts[step * 4096 + b * NW + j];
        sQ[j] = (xb[st + WS] > thr) ? 1.f : 0.f;
    }
    __syncthreads();

    if (j == 0) {
        float mx = -1e30f;
        for (int m = 0; m < NW; m++) mx = fmaxf(mx, sE[m]);
        float ssum = 0.f, s = 0.f;
        for (int m = 0; m < NW; m++) {
            float a = __expf(sE[m] - mx);
            ssum += a;
            if (sQ[m] > 0.5f) s += a;
        }
        s /= ssum;
        float u = 1.f / (1.f + __expf(-(s * Wc[0] + bc[0])));
        float y = g_o[b] + u;
        g_xbuf[b][T] = y;
        out[b * PL + step]              = y;  // pred (B,4,1)
        out[BATCH * PL + b * PL + step] = u;  // us   (B,4,1)
    }
}

// ---------------- launch ----------------
extern "C" void kernel_launch(void* const* d_in, const int* in_sizes, int n_in,
                              void* d_out, int out_size) {
    const float* batch_x = (const float*)d_in[0];
    const float* Wi_g = (const float*)d_in[4];
    const float* Wh_g = (const float*)d_in[5];
    const float* bi_g = (const float*)d_in[6];
    const float* bh_g = (const float*)d_in[7];
    const float* Wi_w = (const float*)d_in[8];
    const float* Wh_w = (const float*)d_in[9];
    const float* bi_w = (const float*)d_in[10];
    const float* bh_w = (const float*)d_in[11];
    const float* Wd   = (const float*)d_in[12];
    const float* bd   = (const float*)d_in[13];
    const float* Wc   = (const float*)d_in[16];
    const float* bc   = (const float*)d_in[17];
    float* out = (float*)d_out;

    copy_x_kernel<<<(BATCH * T0 + 511) / 512, 512>>>(batch_x);
    starts_kernel<<<(PL * 2048 + 255) / 256, 256>>>();

    for (int i = 0; i < PL; i++) {
        int T = T0 + i;
        int Tpass = (i == 0) ? T0 : (T - 1);
        step_kernel<<<BATCH + BATCH * NW / WPB, G3>>>(
            Wh_g, Wi_g, bi_g, bh_g, Wd, bd,
            Wh_w, Wi_w, bi_w, bh_w, i, Tpass);
        finalize_kernel<<<BATCH, 128>>>(Wc, bc, i, T, out);
    }
}